// round 16
// baseline (speedup 1.0000x reference)
#include <cuda_runtime.h>
#include <cuda_bf16.h>
#include <cstdint>
#include <cstddef>

#define NB 4
#define V1 40962
#define V2 163842
#define EPSF 1e-5f
#define SLOPE 0.2f

#if defined(__CUDA_ARCH_FEAT_SM103_ALL) || (defined(__CUDA_ARCH_SPECIFIC__) && (__CUDA_ARCH_SPECIFIC__ == 1030))
#define HAS_TC 1
#else
#define HAS_TC 0
#endif

// ---------------- static scratch ----------------
__device__ float g_raw[(size_t)NB * V1 * 224];
__device__ float g_y  [(size_t)NB * V2 * 64];
__device__ float g_h1 [(size_t)NB * V2 * 32];
__device__ float g_h2 [(size_t)NB * V2 * 32];
__device__ float g_s1[NB * 32], g_q1[NB * 32];
__device__ float g_s2[NB * 32], g_q2[NB * 32];
__device__ float g_sc1[NB * 32], g_sh1[NB * 32];
__device__ float g_sc2[NB * 32], g_sh2[NB * 32];
__device__ float g_W1t[448 * 32];      // FFMA fallback
__device__ float g_W2t[224 * 32];      // FFMA fallback
__device__ float g_Wut[7 * 64 * 32];
__device__ __align__(16) __nv_bfloat16 g_W1h[7 * 2048];
__device__ __align__(16) __nv_bfloat16 g_W1l[7 * 2048];
__device__ __align__(16) __nv_bfloat16 g_W2h[4 * 2048];   // K padded 224->256
__device__ __align__(16) __nv_bfloat16 g_W2l[4 * 2048];

extern __shared__ float smem[];

// ---------------- tcgen05 helpers ----------------
__device__ __forceinline__ uint32_t smem_u32(const void* p) {
    uint32_t a;
    asm("{ .reg .u64 t; cvta.to.shared.u64 t, %1; cvt.u32.u64 %0, t; }" : "=r"(a) : "l"(p));
    return a;
}
#define SWZ128(o) ((o) ^ (((o) >> 3) & 0x70))
static constexpr uint64_t DESC_BASE_SW128 =
    (uint64_t(2) << 61) | (uint64_t(1) << 46) | (uint64_t(64) << 32) | (uint64_t(1) << 16);
#define MK_DESC(a) (DESC_BASE_SW128 | ((uint64_t)((a) >> 4) & 0x3FFF))
#define MMA_IDESC 0x8080490u

#if HAS_TC
__device__ __forceinline__ void mma_f16_ss(uint32_t d, uint64_t a, uint64_t b, uint32_t en) {
    asm volatile(
        "{\n\t.reg .pred p;\n\tsetp.ne.u32 p, %4, 0;\n\t"
        "tcgen05.mma.cta_group::1.kind::f16 [%0], %1, %2, %3, {%5, %5, %5, %5}, p;\n\t}"
        :: "r"(d), "l"(a), "l"(b), "r"(MMA_IDESC), "r"(en), "r"(0u) : "memory");
}
#define TC_ALLOC(sa, n)  asm volatile("tcgen05.alloc.cta_group::1.sync.aligned.shared::cta.b32 [%0], %1;" :: "r"(sa), "r"(n) : "memory")
#define TC_DEALLOC(t, n) asm volatile("tcgen05.dealloc.cta_group::1.sync.aligned.b32 %0, %1;" :: "r"(t), "r"(n))
#define TC_RELINQ()      asm volatile("tcgen05.relinquish_alloc_permit.cta_group::1.sync.aligned;")
#define TC_COMMIT(mb)    asm volatile("tcgen05.commit.cta_group::1.mbarrier::arrive::one.shared::cluster.b64 [%0];" :: "r"(mb) : "memory")
#define TC_FENCE_AFTER() asm volatile("tcgen05.fence::after_thread_sync;" ::: "memory")
#define TC_FENCE_BEFORE() asm volatile("tcgen05.fence::before_thread_sync;" ::: "memory")
#define TC_WAIT_LD()     asm volatile("tcgen05.wait::ld.sync.aligned;" ::: "memory")
#define TC_LD32(r, t) \
    asm volatile("tcgen05.ld.sync.aligned.32x32b.x32.b32 " \
        "{%0,%1,%2,%3,%4,%5,%6,%7,%8,%9,%10,%11,%12,%13,%14,%15," \
        "%16,%17,%18,%19,%20,%21,%22,%23,%24,%25,%26,%27,%28,%29,%30,%31}, [%32];" \
        : "=r"((r)[0]),"=r"((r)[1]),"=r"((r)[2]),"=r"((r)[3]),"=r"((r)[4]),"=r"((r)[5]),"=r"((r)[6]),"=r"((r)[7]), \
          "=r"((r)[8]),"=r"((r)[9]),"=r"((r)[10]),"=r"((r)[11]),"=r"((r)[12]),"=r"((r)[13]),"=r"((r)[14]),"=r"((r)[15]), \
          "=r"((r)[16]),"=r"((r)[17]),"=r"((r)[18]),"=r"((r)[19]),"=r"((r)[20]),"=r"((r)[21]),"=r"((r)[22]),"=r"((r)[23]), \
          "=r"((r)[24]),"=r"((r)[25]),"=r"((r)[26]),"=r"((r)[27]),"=r"((r)[28]),"=r"((r)[29]),"=r"((r)[30]),"=r"((r)[31]) \
        : "r"(t))
#endif

#define MBAR_INIT(mb, n) asm volatile("mbarrier.init.shared.b64 [%0], %1;" :: "r"(mb), "r"(n) : "memory")
#define MBAR_INVAL(mb)   asm volatile("mbarrier.inval.shared.b64 [%0];" :: "r"(mb) : "memory")
#define MBAR_WAIT(mb, ph) do { \
    uint32_t _m = (mb), _p = (ph), _d; \
    asm volatile("{\n\t.reg .pred p;\n\tmbarrier.try_wait.parity.acquire.cta.shared::cta.b64 p, [%1], %2;\n\tselp.b32 %0, 1, 0, p;\n\t}" \
        : "=r"(_d) : "r"(_m), "r"(_p) : "memory"); \
    if (!_d) { \
        asm volatile("{\n\t.reg .pred P1;\n\tWL_%=:\n\tmbarrier.try_wait.parity.acquire.cta.shared::cta.b64 P1, [%0], %1, 0x989680;\n\t@P1 bra.uni WD_%=;\n\tbra.uni WL_%=;\n\tWD_%=:\n\t}" \
            :: "r"(_m), "r"(_p) : "memory"); \
    } } while (0)

// conv1t smem: A bufs are 64KB: [Ah_s0 16K][Ah_s1 16K][Al_s0 16K][Al_s1 16K]
#define SM_TM   0
#define SM_BAR0 8
#define SM_BAR1 16
#define SM_BH   1024
#define SM_BL   (SM_BH + 28672)
#define SM_A    (SM_BL + 28672)
#define SM_BIAS (SM_A + 131072)
#define SM_C1_TOTAL (SM_BIAS + 128 + 1024)
// conv2t smem
#define SM2_BH   1024
#define SM2_BL   (SM2_BH + 16384)
#define SM2_A    (SM2_BL + 16384)
#define SM2_SC   (SM2_A + 131072)
#define SM2_SH   (SM2_SC + 128)
#define SM2_BIAS (SM2_SH + 128)
#define SM_C2_TOTAL (SM2_BIAS + 128 + 1024)

// ---------------- prep ----------------
__global__ __launch_bounds__(256) void k_prep(const float* __restrict__ W1,
                                              const float* __restrict__ W2,
                                              const float* __restrict__ W_up)
{
    int gt = blockIdx.x * 256 + threadIdx.x;
    int stride = gridDim.x * 256;
    if (gt < NB * 32) { g_s1[gt] = 0.f; g_q1[gt] = 0.f; g_s2[gt] = 0.f; g_q2[gt] = 0.f; }
    for (int i = gt; i < 448 * 32; i += stride) {
        int k = i >> 5, c = i & 31;
        g_W1t[i] = W1[c * 448 + k];
    }
    for (int i = gt; i < 224 * 32; i += stride) {
        int k = i >> 5, c = i & 31;
        g_W2t[i] = W2[c * 224 + k];
    }
    for (int i = gt; i < 7 * 64 * 32; i += stride) {
        int rg = i >> 11, rem = i & 2047;
        int k = rem >> 5, c = rem & 31;
        g_Wut[i] = W_up[(rg * 32 + c) * 64 + k];
    }
    for (int i = gt; i < 7 * 2048; i += stride) {
        int j = i >> 11, rem = i & 2047;
        int r = rem >> 6, kk = rem & 63;
        float v = W1[r * 448 + j * 64 + kk];
        __nv_bfloat16 h = __float2bfloat16(v);
        __nv_bfloat16 l = __float2bfloat16(v - __bfloat162float(h));
        uint32_t sw = SWZ128((uint32_t)(r * 128 + kk * 2));
        g_W1h[j * 2048 + (sw >> 1)] = h;
        g_W1l[j * 2048 + (sw >> 1)] = l;
    }
    for (int i = gt; i < 4 * 2048; i += stride) {
        int j = i >> 11, rem = i & 2047;
        int r = rem >> 6, kk = rem & 63;
        int ksrc = j * 64 + kk;
        float v = (ksrc < 224) ? W2[r * 224 + ksrc] : 0.f;
        __nv_bfloat16 h = __float2bfloat16(v);
        __nv_bfloat16 l = __float2bfloat16(v - __bfloat162float(h));
        uint32_t sw = SWZ128((uint32_t)(r * 128 + kk * 2));
        g_W2h[j * 2048 + (sw >> 1)] = h;
        g_W2l[j * 2048 + (sw >> 1)] = l;
    }
}

// ---------------- upconv GEMM (R5) ----------------
__global__ __launch_bounds__(256) void k_upgemm(const float* __restrict__ x1,
                                                const float* __restrict__ b_up)
{
    float* Wt = smem;
    float* bs = Wt + 7 * 64 * 32;
    float* mblk = bs + 224;
    float* sblk = mblk + 8 * 32 * 65;
    int tid = threadIdx.x, b = blockIdx.y;

    for (int i = tid; i < 7 * 64 * 32; i += 256) Wt[i] = g_Wut[i];
    for (int i = tid; i < 224; i += 256) bs[i] = b_up[i];
    __syncthreads();

    int warp = tid >> 5, lane = tid & 31;
    int tb = (blockIdx.x * 8 + warp) * 32;
    if (tb >= V1) return;
    int nvalid = V1 - tb; if (nvalid > 32) nvalid = 32;
    float* m = mblk + warp * 32 * 65;
    float* st = sblk + warp * 32 * 33;
    const float* x1b = x1 + (size_t)b * 64 * V1;
    float* rb = g_raw + (size_t)b * V1 * 224;

    {
        int v = tb + lane;
        bool ok = (lane < nvalid);
#pragma unroll 8
        for (int c = 0; c < 64; ++c)
            m[lane * 65 + c] = ok ? x1b[(size_t)c * V1 + v] : 0.f;
    }
    __syncwarp();

    const float* mp = m + lane * 65;
    for (int rg = 0; rg < 7; ++rg) {
        float acc[32];
#pragma unroll
        for (int q = 0; q < 8; ++q) {
            float4 b4 = *(const float4*)(bs + rg * 32 + 4 * q);
            acc[4 * q] = b4.x; acc[4 * q + 1] = b4.y;
            acc[4 * q + 2] = b4.z; acc[4 * q + 3] = b4.w;
        }
        const float* wp = Wt + rg * 64 * 32;
#pragma unroll 8
        for (int k = 0; k < 64; ++k) {
            float xm = mp[k];
            const float* w = wp + k * 32;
#pragma unroll
            for (int q = 0; q < 8; ++q) {
                float4 w4 = *(const float4*)(w + 4 * q);
                acc[4 * q]     = fmaf(xm, w4.x, acc[4 * q]);
                acc[4 * q + 1] = fmaf(xm, w4.y, acc[4 * q + 1]);
                acc[4 * q + 2] = fmaf(xm, w4.z, acc[4 * q + 2]);
                acc[4 * q + 3] = fmaf(xm, w4.w, acc[4 * q + 3]);
            }
        }
#pragma unroll
        for (int c = 0; c < 32; ++c) st[lane * 33 + c] = acc[c];
        __syncwarp();
#pragma unroll
        for (int r = 0; r < 8; ++r) {
            int v = 4 * r + (lane >> 3);
            int c = 4 * (lane & 7);
            if (v < nvalid) {
                float4 o = make_float4(st[v * 33 + c], st[v * 33 + c + 1],
                                       st[v * 33 + c + 2], st[v * 33 + c + 3]);
                *(float4*)(rb + (size_t)(tb + v) * 224 + rg * 32 + c) = o;
            }
        }
        __syncwarp();
    }
}

// ---------------- scatter + skip concat (R5) ----------------
__global__ __launch_bounds__(256) void k_scatter(const float* __restrict__ x2,
                                                 const int* __restrict__ top,
                                                 const int* __restrict__ down)
{
    int b = blockIdx.y;
    int v0 = blockIdx.x * 256;
    const float* fb = g_raw + (size_t)b * V1 * 224;
    float* yb = g_y + (size_t)b * V2 * 64;
    int tid = threadIdx.x;
    for (int pass = 0; pass < 8; ++pass) {
        int vl = pass * 32 + (tid >> 3);
        int v = v0 + vl;
        int c0 = 4 * (tid & 7);
        if (v < V1) {
            int t = top[v];
            float4 f = *(const float4*)(fb + (size_t)t * 32 + c0);
            *(float4*)(yb + (size_t)v * 64 + c0) = f;
        } else if (v < V2) {
            int n = v - V1;
            int r = down[2 * n + (c0 >= 16 ? 1 : 0)];
            int base = (2 * c0) & 31;
            float4 f0 = *(const float4*)(fb + (size_t)r * 32 + base);
            float4 f1 = *(const float4*)(fb + (size_t)r * 32 + base + 4);
            float4 o;
            o.x = 0.5f * (f0.x + f0.y); o.y = 0.5f * (f0.z + f0.w);
            o.z = 0.5f * (f1.x + f1.y); o.w = 0.5f * (f1.z + f1.w);
            *(float4*)(yb + (size_t)v * 64 + c0) = o;
        }
    }
    const float* x2b = x2 + (size_t)b * 32 * V2;
    for (int i = tid; i < 256 * 32; i += 256) {
        int c = i & 31, vl = i >> 5;
        int v = v0 + vl;
        if (v < V2) yb[(size_t)v * 64 + 32 + c] = x2b[(size_t)c * V2 + v];
    }
}

#define C1_NTILES ((V2 + 127) / 128)
#define C1_TOTAL_TILES (C1_NTILES * NB)

#if HAS_TC
// packed bf16 split of 16 floats -> one 64B hi store + one 64B lo store
__device__ __forceinline__ void split_sts(const float4* rc, char* Ah, char* Al,
                                          uint32_t off0, uint32_t off1)
{
#pragma unroll
    for (int st = 0; st < 2; ++st) {
        float4 fa = rc[2 * st], fb2 = rc[2 * st + 1];
        float fv[8] = {fa.x, fa.y, fa.z, fa.w, fb2.x, fb2.y, fb2.z, fb2.w};
        uint32_t hw[4], lw[4];
#pragma unroll
        for (int p = 0; p < 4; ++p) {
            float f0 = fv[2 * p], f1 = fv[2 * p + 1];
            uint32_t h;
            asm("cvt.rn.bf16x2.f32 %0, %1, %2;" : "=r"(h) : "f"(f1), "f"(f0));
            float h0 = __uint_as_float(h << 16);
            float h1 = __uint_as_float(h & 0xffff0000u);
            uint32_t l;
            asm("cvt.rn.bf16x2.f32 %0, %1, %2;" : "=r"(l) : "f"(f1 - h1), "f"(f0 - h0));
            hw[p] = h; lw[p] = l;
        }
        uint32_t off = st ? off1 : off0;
        *(uint4*)(Ah + off) = make_uint4(hw[0], hw[1], hw[2], hw[3]);
        *(uint4*)(Al + off) = make_uint4(lw[0], lw[1], lw[2], lw[3]);
    }
}
#endif

// ---------------- conv1 (tensor): persistent, 2 neighbors/round ----------------
__global__ __launch_bounds__(512)
void k_conv1t(const int* __restrict__ neigh, const float* __restrict__ b1)
{
#if HAS_TC
    char* sb0 = (char*)smem;
    uint32_t su0 = smem_u32(sb0);
    uint32_t pad = ((su0 + 1023u) & ~1023u) - su0;
    char* sb = sb0 + pad;
    uint32_t su = su0 + pad;

    int tid = threadIdx.x, wid = tid >> 5, lane = tid & 31;

    if (wid == 0) { TC_ALLOC(su + SM_TM, 128); TC_RELINQ(); }
    if (tid == 128) { MBAR_INIT(su + SM_BAR0, 1); MBAR_INIT(su + SM_BAR1, 1); }

    {
        const uint4* srcH = (const uint4*)g_W1h;
        const uint4* srcL = (const uint4*)g_W1l;
        uint4* dstH = (uint4*)(sb + SM_BH);
        uint4* dstL = (uint4*)(sb + SM_BL);
        for (int i = tid; i < 1792; i += 512) { dstH[i] = srcH[i]; dstL[i] = srcL[i]; }
    }
    if (tid < 32) ((float*)(sb + SM_BIAS))[tid] = b1[tid];
    __syncthreads();

    uint32_t tmem_base;
    asm volatile("ld.shared.b32 %0, [%1];" : "=r"(tmem_base) : "r"(su + SM_TM));

    int row = tid >> 2;
    int quarter = tid & 3;
    int par0 = 0, par1 = 0;
    uint32_t swoff0 = SWZ128((uint32_t)(row * 128 + (quarter * 16 + 0) * 2));
    uint32_t swoff1 = SWZ128((uint32_t)(row * 128 + (quarter * 16 + 8) * 2));

    for (int t = blockIdx.x; t < C1_TOTAL_TILES; t += gridDim.x) {
        int b = t / C1_NTILES;
        int tb = (t % C1_NTILES) * 128;
        int nvalid = V2 - tb; if (nvalid > 128) nvalid = 128;
        const float* yb = g_y + (size_t)b * V2 * 64;
        bool rv = (row < nvalid);

        int nbs[7];
        {
            const int* np = neigh + (size_t)(tb + (rv ? row : 0)) * 7;
#pragma unroll
            for (int q = 0; q < 7; ++q) nbs[q] = np[q];
        }

        float4 rcA[4], rcB[4];
        {
            const float* sa = yb + (size_t)nbs[0] * 64 + quarter * 16;
            const float* sbp = yb + (size_t)nbs[1] * 64 + quarter * 16;
#pragma unroll
            for (int g = 0; g < 4; ++g) {
                rcA[g] = rv ? *(const float4*)(sa + 4 * g) : make_float4(0.f, 0.f, 0.f, 0.f);
                rcB[g] = rv ? *(const float4*)(sbp + 4 * g) : make_float4(0.f, 0.f, 0.f, 0.f);
            }
        }

        for (int r = 0; r < 4; ++r) {
            int buf = r & 1;
            if (r == 2) { MBAR_WAIT(su + SM_BAR0, par0); par0 ^= 1; }
            if (r == 3) { MBAR_WAIT(su + SM_BAR1, par1); par1 ^= 1; }
            char* base = sb + SM_A + buf * 65536;
            // neighbor A -> subtile 0
            split_sts(rcA, base, base + 32768, swoff0, swoff1);
            if (r < 3) {
                const float* sa = yb + (size_t)nbs[2 * r + 2] * 64 + quarter * 16;
#pragma unroll
                for (int g = 0; g < 4; ++g)
                    rcA[g] = rv ? *(const float4*)(sa + 4 * g) : make_float4(0.f, 0.f, 0.f, 0.f);
            }
            // neighbor B -> subtile 1 (rounds 0..2)
            if (r < 3) {
                split_sts(rcB, base + 16384, base + 49152, swoff0, swoff1);
                if (r < 2) {
                    const float* sbp = yb + (size_t)nbs[2 * r + 3] * 64 + quarter * 16;
#pragma unroll
                    for (int g = 0; g < 4; ++g)
                        rcB[g] = rv ? *(const float4*)(sbp + 4 * g) : make_float4(0.f, 0.f, 0.f, 0.f);
                }
            }
            __syncthreads();
            if (tid == 0) {
                asm volatile("fence.proxy.async.shared::cta;" ::: "memory");
                uint32_t ab = su + SM_A + buf * 65536;
                int nsub = (r < 3) ? 2 : 1;
                for (int sub = 0; sub < nsub; ++sub) {
                    int chunk = 2 * r + sub;
                    uint64_t ah = MK_DESC(ab + sub * 16384);
                    uint64_t al = MK_DESC(ab + 32768 + sub * 16384);
                    uint64_t bh = MK_DESC(su + SM_BH + chunk * 4096);
                    uint64_t bl = MK_DESC(su + SM_BL + chunk * 4096);
#pragma unroll
                    for (int s = 0; s < 4; ++s)
                        mma_f16_ss(tmem_base, ah + 2 * s, bh + 2 * s,
                                   !(r == 0 && sub == 0 && s == 0));
#pragma unroll
                    for (int s = 0; s < 4; ++s)
                        mma_f16_ss(tmem_base, al + 2 * s, bh + 2 * s, 1u);
#pragma unroll
                    for (int s = 0; s < 4; ++s)
                        mma_f16_ss(tmem_base, ah + 2 * s, bl + 2 * s, 1u);
                }
                TC_COMMIT(su + (buf ? SM_BAR1 : SM_BAR0));
            }
        }
        // tile-end: wait last commit (r3 on bar1) -> covers all MMAs.
        MBAR_WAIT(su + SM_BAR1, par1); par1 ^= 1;
        par0 ^= 1;   // silent flip for unwaited r2 commit on bar0
        TC_FENCE_AFTER();

        if (tid < 128) {
            uint32_t d_regs[32];
            TC_LD32(d_regs, tmem_base);
            TC_WAIT_LD();
            TC_FENCE_BEFORE();
            const float* bias = (const float*)(sb + SM_BIAS);
            int myrow = wid * 32 + lane;
            bool valid = (myrow < nvalid);
            float vals[32];
#pragma unroll
            for (int c = 0; c < 32; ++c)
                vals[c] = valid ? (__uint_as_float(d_regs[c]) + bias[c]) : 0.f;
            if (valid) {
                float* d = g_h1 + (size_t)b * V2 * 32 + (size_t)(tb + myrow) * 32;
#pragma unroll
                for (int qq = 0; qq < 8; ++qq)
                    *(float4*)(d + 4 * qq) = make_float4(vals[4 * qq], vals[4 * qq + 1],
                                                         vals[4 * qq + 2], vals[4 * qq + 3]);
            }
            float qv[32];
#pragma unroll
            for (int c = 0; c < 32; ++c) qv[c] = vals[c] * vals[c];
#pragma unroll
            for (int d = 1; d < 32; d <<= 1) {
#pragma unroll
                for (int c = 0; c < 32; ++c) {
                    vals[c] += __shfl_xor_sync(0xffffffffu, vals[c], d);
                    qv[c]   += __shfl_xor_sync(0xffffffffu, qv[c], d);
                }
            }
            atomicAdd(&g_s1[b * 32 + lane], vals[lane]);
            atomicAdd(&g_q1[b * 32 + lane], qv[lane]);
        }
        __syncthreads();
    }

    if (tid == 128) { MBAR_INVAL(su + SM_BAR0); MBAR_INVAL(su + SM_BAR1); }
    __syncthreads();
    if (wid == 0) TC_DEALLOC(tmem_base, 128);
#endif
}

// ---------------- conv2 (tensor): persistent, 4 neighbors/round, 2 rounds ----------------
__global__ __launch_bounds__(512)
void k_conv2t(const int* __restrict__ neigh, const float* __restrict__ b2)
{
#if HAS_TC
    char* sb0 = (char*)smem;
    uint32_t su0 = smem_u32(sb0);
    uint32_t pad = ((su0 + 1023u) & ~1023u) - su0;
    char* sb = sb0 + pad;
    uint32_t su = su0 + pad;

    int tid = threadIdx.x, wid = tid >> 5, lane = tid & 31;

    if (wid == 0) { TC_ALLOC(su + SM_TM, 128); TC_RELINQ(); }
    if (tid == 128) { MBAR_INIT(su + SM_BAR0, 1); MBAR_INIT(su + SM_BAR1, 1); }

    {
        const uint4* srcH = (const uint4*)g_W2h;
        const uint4* srcL = (const uint4*)g_W2l;
        uint4* dstH = (uint4*)(sb + SM2_BH);
        uint4* dstL = (uint4*)(sb + SM2_BL);
        for (int i = tid; i < 1024; i += 512) { dstH[i] = srcH[i]; dstL[i] = srcL[i]; }
    }
    if (tid < 32) ((float*)(sb + SM2_BIAS))[tid] = b2[tid];
    __syncthreads();

    uint32_t tmem_base;
    asm volatile("ld.shared.b32 %0, [%1];" : "=r"(tmem_base) : "r"(su + SM_TM));

    int row = tid >> 2;
    int quarter = tid & 3;
    int sub = quarter >> 1;          // K64 subtile
    int slot = quarter & 1;          // neighbor slot within subtile
    int par0 = 0, par1 = 0;
    uint32_t swo[4];
#pragma unroll
    for (int i = 0; i < 4; ++i)
        swo[i] = SWZ128((uint32_t)(row * 128 + slot * 64 + 16 * i));
    const float* sc_s = (const float*)(sb + SM2_SC);
    const float* sh_s = (const float*)(sb + SM2_SH);

    for (int t = blockIdx.x; t < C1_TOTAL_TILES; t += gridDim.x) {
        int b = t / C1_NTILES;
        int tb = (t % C1_NTILES) * 128;
        int nvalid = V2 - tb; if (nvalid > 128) nvalid = 128;
        const float* h1b = g_h1 + (size_t)b * V2 * 32;
        bool rv = (row < nvalid);

        if (tid < 32) {
            ((float*)(sb + SM2_SC))[tid] = g_sc1[b * 32 + tid];
            ((float*)(sb + SM2_SH))[tid] = g_sh1[b * 32 + tid];
        }

        int nbs[7];
        {
            const int* np = neigh + (size_t)(tb + (rv ? row : 0)) * 7;
#pragma unroll
            for (int q = 0; q < 7; ++q) nbs[q] = np[q];
        }
        __syncthreads();   // sc_s/sh_s visible; also separates from prev tile epilogue

        // round 0 gather: neighbor = quarter (n0..n3), 32 channels
        float4 rc[8];
        {
            const float* src = h1b + (size_t)nbs[quarter] * 32;
#pragma unroll
            for (int g = 0; g < 8; ++g)
                rc[g] = rv ? *(const float4*)(src + 4 * g) : make_float4(0.f, 0.f, 0.f, 0.f);
        }

        for (int r = 0; r < 2; ++r) {
            int buf = r;
            char* base = sb + SM2_A + buf * 65536;
            char* Ah = base + sub * 16384;
            char* Al = base + 32768 + sub * 16384;
            // BN fold + split + STS (4 stores per plane)
#pragma unroll
            for (int st = 0; st < 4; ++st) {
                float4 f0 = rc[2 * st], f1 = rc[2 * st + 1];
                float4 sc0 = *(const float4*)(sc_s + 8 * st);
                float4 sh0 = *(const float4*)(sh_s + 8 * st);
                float4 sc1 = *(const float4*)(sc_s + 8 * st + 4);
                float4 sh1 = *(const float4*)(sh_s + 8 * st + 4);
                f0.x = fmaf(f0.x, sc0.x, sh0.x); f0.x = f0.x >= 0.f ? f0.x : SLOPE * f0.x;
                f0.y = fmaf(f0.y, sc0.y, sh0.y); f0.y = f0.y >= 0.f ? f0.y : SLOPE * f0.y;
                f0.z = fmaf(f0.z, sc0.z, sh0.z); f0.z = f0.z >= 0.f ? f0.z : SLOPE * f0.z;
                f0.w = fmaf(f0.w, sc0.w, sh0.w); f0.w = f0.w >= 0.f ? f0.w : SLOPE * f0.w;
                f1.x = fmaf(f1.x, sc1.x, sh1.x); f1.x = f1.x >= 0.f ? f1.x : SLOPE * f1.x;
                f1.y = fmaf(f1.y, sc1.y, sh1.y); f1.y = f1.y >= 0.f ? f1.y : SLOPE * f1.y;
                f1.z = fmaf(f1.z, sc1.z, sh1.z); f1.z = f1.z >= 0.f ? f1.z : SLOPE * f1.z;
                f1.w = fmaf(f1.w, sc1.w, sh1.w); f1.w = f1.w >= 0.f ? f1.w : SLOPE * f1.w;
                float fv[8] = {f0.x, f0.y, f0.z, f0.w, f1.x, f1.y, f1.z, f1.w};
                uint32_t hw[4], lw[4];
#pragma unroll
                for (int p = 0; p < 4; ++p) {
                    float a0 = fv[2 * p], a1 = fv[2 * p + 1];
                    uint32_t h;
                    asm("cvt.rn.bf16x2.f32 %0, %1, %2;" : "=r"(h) : "f"(a1), "f"(a0));
                    float h0 = __uint_as_float(h << 16);
                    float h1f = __uint_as_float(h & 0xffff0000u);
                    uint32_t l;
                    asm("cvt.rn.bf16x2.f32 %0, %1, %2;" : "=r"(l) : "f"(a1 - h1f), "f"(a0 - h0));
                    hw[p] = h; lw[p] = l;
                }
                *(uint4*)(Ah + swo[st]) = make_uint4(hw[0], hw[1], hw[2], hw[3]);
                *(uint4*)(Al + swo[st]) = make_uint4(lw[0], lw[1], lw[2], lw[3]);
            }
            // round 1 gather: neighbor = 4 + quarter (n4..n6 + pad dup of n6)
            if (r == 0) {
                int nn = 4 + quarter;
                int nb = nbs[nn < 7 ? nn : 6];
                const float* src = h1b + (size_t)nb * 32;
#pragma unroll
                for (int g = 0; g < 8; ++g)
                    rc[g] = rv ? *(const float4*)(src + 4 * g) : make_float4(0.f, 0.f, 0.f, 0.f);
            }
            __syncthreads();
            if (tid == 0) {
                asm volatile("fence.proxy.async.shared::cta;" ::: "memory");
                uint32_t ab = su + SM2_A + buf * 65536;
                for (int s2 = 0; s2 < 2; ++s2) {
                    int chunk = 2 * r + s2;
                    uint64_t ah = MK_DESC(ab + s2 * 16384);
                    uint64_t al = MK_DESC(ab + 32768 + s2 * 16384);
                    uint64_t bh = MK_DESC(su + SM2_BH + chunk * 4096);
                    uint64_t bl = MK_DESC(su + SM2_BL + chunk * 4096);
#pragma unroll
                    for (int s = 0; s < 4; ++s)
                        mma_f16_ss(tmem_base, ah + 2 * s, bh + 2 * s,
                                   !(r == 0 && s2 == 0 && s == 0));
#pragma unroll
                    for (int s = 0; s < 4; ++s)
                        mma_f16_ss(tmem_base, al + 2 * s, bh + 2 * s, 1u);
#pragma unroll
                    for (int s = 0; s < 4; ++s)
                        mma_f16_ss(tmem_base, ah + 2 * s, bl + 2 * s, 1u);
                }
                TC_COMMIT(su + (buf ? SM_BAR1 : SM_BAR0));
            }
        }
        // tile-end: wait last commit (r1 on bar1); silent flip for r0 on bar0
        MBAR_WAIT(su + SM_BAR1, par1); par1 ^= 1;
        par0 ^= 1;
        TC_FENCE_AFTER();

        if (tid < 128) {
            uint32_t d_regs[32];
            TC_LD32(d_regs, tmem_base);
            TC_WAIT_LD();
            TC_FENCE_BEFORE();
            const float* bias = (const float*)(sb + SM2_BIAS);
            int myrow = wid * 32 + lane;
            bool valid = (myrow < nvalid);
            float vals[32];
#pragma unroll
            for (int c = 0; c < 32; ++c)
                vals[c] = valid ? (__uint_as_float(d_regs[c]) + bias[c]) : 0.f;
            if (valid) {
                float* d = g_h2 + (size_t)b * V2 * 32 + (size_t)(tb + myrow) * 32;
#pragma unroll
                for (int qq = 0; qq < 8; ++qq)
                    *(float4*)(d + 4 * qq) = make_float4(vals[4 * qq], vals[4 * qq + 1],
                                                         vals[4 * qq + 2], vals[4 * qq + 3]);
            }
            float qv[32];
#pragma unroll
            for (int c = 0; c < 32; ++c) qv[c] = vals[c] * vals[c];
#pragma unroll
            for (int d = 1; d < 32; d <<= 1) {
#pragma unroll
                for (int c = 0; c < 32; ++c) {
                    vals[c] += __shfl_xor_sync(0xffffffffu, vals[c], d);
                    qv[c]   += __shfl_xor_sync(0xffffffffu, qv[c], d);
                }
            }
            atomicAdd(&g_s2[b * 32 + lane], vals[lane]);
            atomicAdd(&g_q2[b * 32 + lane], qv[lane]);
        }
        __syncthreads();
    }

    if (tid == 128) { MBAR_INVAL(su + SM_BAR0); MBAR_INVAL(su + SM_BAR1); }
    __syncthreads();
    if (wid == 0) TC_DEALLOC(tmem_base, 128);
#endif
}

// ---------------- FFMA fallbacks (body only without tcgen05) ----------------
__global__ __launch_bounds__(512) void k_conv1f(const int* __restrict__ neigh,
                                                const float* __restrict__ b1)
{
#if !HAS_TC
    float* Wt = smem;
    float* mblk = Wt + 448 * 32;
    int* nblk = (int*)(mblk + 16 * 2112);
    int tid = threadIdx.x, b = blockIdx.y;
    for (int i = tid; i < 448 * 32; i += 512) Wt[i] = g_W1t[i];
    __syncthreads();
    int warp = tid >> 5, lane = tid & 31;
    int tb = (blockIdx.x * 16 + warp) * 32;
    if (tb >= V2) return;
    int nvalid = V2 - tb; if (nvalid > 32) nvalid = 32;
    float* mw = mblk + warp * 2112;
    int* nidxT = nblk + warp * 224;
    const float* yb = g_y + (size_t)b * V2 * 64;
    float* hb = g_h1 + (size_t)b * V2 * 32;
    {
        int vv = tb + (lane < nvalid ? lane : 0);
#pragma unroll
        for (int q = 0; q < 7; ++q)
            nidxT[q * 32 + lane] = neigh[(size_t)vv * 7 + q];
    }
    __syncwarp();
    float acc[32];
#pragma unroll
    for (int q = 0; q < 8; ++q) {
        float4 b4 = *(const float4*)(b1 + 4 * q);
        acc[4 * q] = b4.x; acc[4 * q + 1] = b4.y;
        acc[4 * q + 2] = b4.z; acc[4 * q + 3] = b4.w;
    }
    int rsel = lane >> 3;
    int cg = 4 * (lane & 7);
    const float* mp0 = mw + lane * 33;
    float4 pf[8];
#pragma unroll
    for (int r = 0; r < 8; ++r) {
        int nb = nidxT[4 * r + rsel];
        pf[r] = *(const float4*)(yb + (size_t)nb * 64 + cg);
    }
#pragma unroll
    for (int r = 0; r < 8; ++r) {
        int v = 4 * r + rsel;
        float* d = mw + v * 33 + cg;
        d[0] = pf[r].x; d[1] = pf[r].y; d[2] = pf[r].z; d[3] = pf[r].w;
    }
#pragma unroll
    for (int r = 0; r < 8; ++r) {
        int nb = nidxT[4 * r + rsel];
        pf[r] = *(const float4*)(yb + (size_t)nb * 64 + 32 + cg);
    }
    __syncwarp();
    for (int ch = 0; ch < 14; ++ch) {
        const float* mp = mp0 + (ch & 1) * 1056;
        const float* wp = Wt + ch * 32 * 32;
#pragma unroll 8
        for (int kk = 0; kk < 32; ++kk) {
            float xm = mp[kk];
            const float* w = wp + kk * 32;
#pragma unroll
            for (int q = 0; q < 8; ++q) {
                float4 w4 = *(const float4*)(w + 4 * q);
                acc[4 * q]     = fmaf(xm, w4.x, acc[4 * q]);
                acc[4 * q + 1] = fmaf(xm, w4.y, acc[4 * q + 1]);
                acc[4 * q + 2] = fmaf(xm, w4.z, acc[4 * q + 2]);
                acc[4 * q + 3] = fmaf(xm, w4.w, acc[4 * q + 3]);
            }
        }
        if (ch < 13) {
            float* dbuf = mw + ((ch + 1) & 1) * 1056;
#pragma unroll
            for (int r = 0; r < 8; ++r) {
                int v = 4 * r + rsel;
                float* d = dbuf + v * 33 + cg;
                d[0] = pf[r].x; d[1] = pf[r].y; d[2] = pf[r].z; d[3] = pf[r].w;
            }
            if (ch < 12) {
                int nc = ch + 2;
                int j = nc >> 1;
                int bc = ((nc & 1) << 5) + cg;
#pragma unroll
                for (int r = 0; r < 8; ++r) {
                    int nb = nidxT[j * 32 + 4 * r + rsel];
                    pf[r] = *(const float4*)(yb + (size_t)nb * 64 + bc);
                }
            }
            __syncwarp();
        }
    }
    __syncwarp();
    if (lane >= nvalid) {
#pragma unroll
        for (int c = 0; c < 32; ++c) acc[c] = 0.f;
    }
    float* st = mw;
#pragma unroll
    for (int c = 0; c < 32; ++c) st[lane * 33 + c] = acc[c];
    __syncwarp();
#pragma unroll
    for (int r = 0; r < 8; ++r) {
        int v = 4 * r + rsel;
        if (v < nvalid) {
            float4 o = make_float4(st[v * 33 + cg], st[v * 33 + cg + 1],
                                   st[v * 33 + cg + 2], st[v * 33 + cg + 3]);
            *(float4*)(hb + (size_t)(tb + v) * 32 + cg) = o;
        }
    }
    float s = 0.f, q = 0.f;
#pragma unroll 8
    for (int v = 0; v < 32; ++v) {
        float x = st[v * 33 + lane];
        s += x;
        q = fmaf(x, x, q);
    }
    atomicAdd(&g_s1[b * 32 + lane], s);
    atomicAdd(&g_q1[b * 32 + lane], q);
#endif
}

__global__ __launch_bounds__(512) void k_conv2f(const int* __restrict__ neigh,
                                                const float* __restrict__ b2)
{
#if !HAS_TC
    float* Wt = smem;
    float* mblk = Wt + 224 * 32;
    int* nblk = (int*)(mblk + 16 * 2112);
    int tid = threadIdx.x, b = blockIdx.y;
    for (int i = tid; i < 224 * 32; i += 512) Wt[i] = g_W2t[i];
    __syncthreads();
    int warp = tid >> 5, lane = tid & 31;
    int tb = (blockIdx.x * 16 + warp) * 32;
    if (tb >= V2) return;
    int nvalid = V2 - tb; if (nvalid > 32) nvalid = 32;
    float* mw = mblk + warp * 2112;
    int* nidxT = nblk + warp * 224;
    const float* h1b = g_h1 + (size_t)b * V2 * 32;
    float* h2b = g_h2 + (size_t)b * V2 * 32;
    {
        int vv = tb + (lane < nvalid ? lane : 0);
#pragma unroll
        for (int q = 0; q < 7; ++q)
            nidxT[q * 32 + lane] = neigh[(size_t)vv * 7 + q];
    }
    __syncwarp();
    int rsel = lane >> 3;
    int cg = 4 * (lane & 7);
    float4 sc4 = *(const float4*)(g_sc1 + b * 32 + cg);
    float4 sh4 = *(const float4*)(g_sh1 + b * 32 + cg);
    float acc[32];
#pragma unroll
    for (int q = 0; q < 8; ++q) {
        float4 b4 = *(const float4*)(b2 + 4 * q);
        acc[4 * q] = b4.x; acc[4 * q + 1] = b4.y;
        acc[4 * q + 2] = b4.z; acc[4 * q + 3] = b4.w;
    }
    const float* mp0 = mw + lane * 33;
    float4 pf[8];
#pragma unroll
    for (int r = 0; r < 8; ++r) {
        int nb = nidxT[4 * r + rsel];
        pf[r] = *(const float4*)(h1b + (size_t)nb * 32 + cg);
    }
#pragma unroll
    for (int r = 0; r < 8; ++r) {
        int v = 4 * r + rsel;
        float4 f = pf[r];
        f.x = fmaf(f.x, sc4.x, sh4.x); f.x = f.x >= 0.f ? f.x : SLOPE * f.x;
        f.y = fmaf(f.y, sc4.y, sh4.y); f.y = f.y >= 0.f ? f.y : SLOPE * f.y;
        f.z = fmaf(f.z, sc4.z, sh4.z); f.z = f.z >= 0.f ? f.z : SLOPE * f.z;
        f.w = fmaf(f.w, sc4.w, sh4.w); f.w = f.w >= 0.f ? f.w : SLOPE * f.w;
        float* d = mw + v * 33 + cg;
        d[0] = f.x; d[1] = f.y; d[2] = f.z; d[3] = f.w;
    }
#pragma unroll
    for (int r = 0; r < 8; ++r) {
        int nb = nidxT[32 + 4 * r + rsel];
        pf[r] = *(const float4*)(h1b + (size_t)nb * 32 + cg);
    }
    __syncwarp();
    for (int ch = 0; ch < 7; ++ch) {
        const float* mp = mp0 + (ch & 1) * 1056;
        const float* wp = Wt + ch * 32 * 32;
#pragma unroll 8
        for (int kk = 0; kk < 32; ++kk) {
            float xm = mp[kk];
            const float* w = wp + kk * 32;
#pragma unroll
            for (int q = 0; q < 8; ++q) {
                float4 w4 = *(const float4*)(w + 4 * q);
                acc[4 * q]     = fmaf(xm, w4.x, acc[4 * q]);
                acc[4 * q + 1] = fmaf(xm, w4.y, acc[4 * q + 1]);
                acc[4 * q + 2] = fmaf(xm, w4.z, acc[4 * q + 2]);
                acc[4 * q + 3] = fmaf(xm, w4.w, acc[4 * q + 3]);
            }
        }
        if (ch < 6) {
            float* dbuf = mw + ((ch + 1) & 1) * 1056;
#pragma unroll
            for (int r = 0; r < 8; ++r) {
                int v = 4 * r + rsel;
                float4 f = pf[r];
                f.x = fmaf(f.x, sc4.x, sh4.x); f.x = f.x >= 0.f ? f.x : SLOPE * f.x;
                f.y = fmaf(f.y, sc4.y, sh4.y); f.y = f.y >= 0.f ? f.y : SLOPE * f.y;
                f.z = fmaf(f.z, sc4.z, sh4.z); f.z = f.z >= 0.f ? f.z : SLOPE * f.z;
                f.w = fmaf(f.w, sc4.w, sh4.w); f.w = f.w >= 0.f ? f.w : SLOPE * f.w;
                float* d = dbuf + v * 33 + cg;
                d[0] = f.x; d[1] = f.y; d[2] = f.z; d[3] = f.w;
            }
            if (ch < 5) {
                int j = ch + 2;
#pragma unroll
                for (int r = 0; r < 8; ++r) {
                    int nb = nidxT[j * 32 + 4 * r + rsel];
                    pf[r] = *(const float4*)(h1b + (size_t)nb * 32 + cg);
                }
            }
            __syncwarp();
        }
    }
    __syncwarp();
    if (lane >= nvalid) {
#pragma unroll
        for (int c = 0; c < 32; ++c) acc[c] = 0.f;
    }
    float* st = mw;
#pragma unroll
    for (int c = 0; c < 32; ++c) st[lane * 33 + c] = acc[c];
    __syncwarp();
#pragma unroll
    for (int r = 0; r < 8; ++r) {
        int v = 4 * r + rsel;
        if (v < nvalid) {
            float4 o = make_float4(st[v * 33 + cg], st[v * 33 + cg + 1],
                                   st[v * 33 + cg + 2], st[v * 33 + cg + 3]);
            *(float4*)(h2b + (size_t)(tb + v) * 32 + cg) = o;
        }
    }
    float s = 0.f, q = 0.f;
#pragma unroll 8
    for (int v = 0; v < 32; ++v) {
        float x = st[v * 33 + lane];
        s += x;
        q = fmaf(x, x, q);
    }
    atomicAdd(&g_s2[b * 32 + lane], s);
    atomicAdd(&g_q2[b * 32 + lane], q);
#endif
}

// ---------------- BN finalize ----------------
__global__ void k_bnfin(int which, const float* __restrict__ g, const float* __restrict__ be)
{
    int i = threadIdx.x;
    if (i >= NB * 32) return;
    int c = i & 31;
    float s = which ? g_s2[i] : g_s1[i];
    float q = which ? g_q2[i] : g_q1[i];
    float mean = s / (float)V2;
    float var = q / (float)V2 - mean * mean;
    float scale = g[c] * rsqrtf(var + EPSF);
    float shift = be[c] - mean * scale;
    if (which) { g_sc2[i] = scale; g_sh2[i] = shift; }
    else       { g_sc1[i] = scale; g_sh1[i] = shift; }
}

// ---------------- BN2 + LReLU + transpose out ----------------
__global__ __launch_bounds__(256) void k_final(float* __restrict__ out)
{
    __shared__ float tile[32 * 33];
    int b = blockIdx.y, v0 = blockIdx.x * 32;
    const float* hb = g_h2 + (size_t)b * V2 * 32;
    int tid = threadIdx.x;
    for (int i = tid; i < 1024; i += 256) {
        int c = i & 31, vi = i >> 5;
        int v = v0 + vi;
        tile[vi * 33 + c] = (v < V2) ? hb[(size_t)v * 32 + c] : 0.f;
    }
    __syncthreads();
    for (int i = tid; i < 1024; i += 256) {
        int vi = i & 31, c = i >> 5;
        int v = v0 + vi;
        if (v < V2) {
            float y = fmaf(tile[vi * 33 + c], g_sc2[b * 32 + c], g_sh2[b * 32 + c]);
            out[((size_t)b * 32 + c) * V2 + v] = (y >= 0.f) ? y : SLOPE * y;
        }
    }
}

// ---------------- launch ----------------
extern "C" void kernel_launch(void* const* d_in, const int* in_sizes, int n_in,
                              void* d_out, int out_size)
{
    const float* x1   = (const float*)d_in[0];
    const float* x2   = (const float*)d_in[1];
    const int* neigh  = (const int*)d_in[2];
    const int* top    = (const int*)d_in[3];
    const int* down   = (const int*)d_in[4];
    const float* W_up = (const float*)d_in[5];
    const float* b_up = (const float*)d_in[6];
    const float* W1   = (const float*)d_in[7];
    const float* b1   = (const float*)d_in[8];
    const float* g1   = (const float*)d_in[9];
    const float* be1  = (const float*)d_in[10];
    const float* W2   = (const float*)d_in[11];
    const float* b2   = (const float*)d_in[12];
    const float* g2   = (const float*)d_in[13];
    const float* be2  = (const float*)d_in[14];
    float* out = (float*)d_out;

    const size_t ug_smem = (size_t)(7 * 64 * 32 + 224 + 8 * 32 * 65 + 8 * 32 * 33) * 4;
    const size_t c1t_smem = SM_C1_TOTAL;
    const size_t c2t_smem = SM_C2_TOTAL;
    const size_t c1f_smem = (size_t)(448 * 32 + 16 * 2112 + 16 * 224) * 4;
    const size_t c2f_smem = (size_t)(224 * 32 + 16 * 2112 + 16 * 224) * 4;
    cudaFuncSetAttribute(k_upgemm, cudaFuncAttributeMaxDynamicSharedMemorySize, (int)ug_smem);
    cudaFuncSetAttribute(k_conv1t, cudaFuncAttributeMaxDynamicSharedMemorySize, (int)c1t_smem);
    cudaFuncSetAttribute(k_conv2t, cudaFuncAttributeMaxDynamicSharedMemorySize, (int)c2t_smem);
    cudaFuncSetAttribute(k_conv1f, cudaFuncAttributeMaxDynamicSharedMemorySize, (int)c1f_smem);
    cudaFuncSetAttribute(k_conv2f, cudaFuncAttributeMaxDynamicSharedMemorySize, (int)c2f_smem);

    int nsm = 148;
    cudaDeviceGetAttribute(&nsm, cudaDevAttrMultiProcessorCount, 0);

    k_prep<<<32, 256>>>(W1, W2, W_up);

    int ug_tiles = (V1 + 31) / 32;
    dim3 gug((ug_tiles + 7) / 8, NB);
    k_upgemm<<<gug, 256, ug_smem>>>(x1, b_up);

    dim3 gsc((V2 + 255) / 256, NB);
    k_scatter<<<gsc, 256>>>(x2, top, down);

    int cv_tiles = (V2 + 31) / 32;
    dim3 gcv((cv_tiles + 15) / 16, NB);

    k_conv1t<<<nsm, 512, c1t_smem>>>(neigh, b1);
    k_conv1f<<<gcv, 512, c1f_smem>>>(neigh, b1);

    k_bnfin<<<1, 128>>>(0, g1, be1);

    k_conv2t<<<nsm, 512, c2t_smem>>>(neigh, b2);
    k_conv2f<<<gcv, 512, c2f_smem>>>(neigh, b2);

    k_bnfin<<<1, 128>>>(1, g2, be2);

    dim3 gfin((V2 + 31) / 32, NB);
    k_final<<<gfin, 256>>>(out);
}

// round 17
// speedup vs baseline: 1.0818x; 1.0818x over previous
#include <cuda_runtime.h>
#include <cuda_bf16.h>
#include <cstdint>
#include <cstddef>

#define NB 4
#define V1 40962
#define V2 163842
#define EPSF 1e-5f
#define SLOPE 0.2f

#if defined(__CUDA_ARCH_FEAT_SM103_ALL) || (defined(__CUDA_ARCH_SPECIFIC__) && (__CUDA_ARCH_SPECIFIC__ == 1030))
#define HAS_TC 1
#else
#define HAS_TC 0
#endif

// ---------------- static scratch ----------------
__device__ float g_raw[(size_t)NB * V1 * 224];
__device__ float g_y  [(size_t)NB * V2 * 64];
__device__ float g_h1 [(size_t)NB * V2 * 32];
__device__ float g_h2 [(size_t)NB * V2 * 32];
__device__ float g_s1[NB * 32], g_q1[NB * 32];
__device__ float g_s2[NB * 32], g_q2[NB * 32];
__device__ float g_sc1[NB * 32], g_sh1[NB * 32];
__device__ float g_sc2[NB * 32], g_sh2[NB * 32];
__device__ float g_W1t[448 * 32];      // FFMA fallback
__device__ float g_W2t[224 * 32];      // FFMA fallback
__device__ float g_Wut[7 * 64 * 32];
__device__ __align__(16) __nv_bfloat16 g_W1h[7 * 2048];
__device__ __align__(16) __nv_bfloat16 g_W1l[7 * 2048];
__device__ __align__(16) __nv_bfloat16 g_W2h[4 * 2048];   // K padded 224->256
__device__ __align__(16) __nv_bfloat16 g_W2l[4 * 2048];

extern __shared__ float smem[];

// ---------------- tcgen05 helpers ----------------
__device__ __forceinline__ uint32_t smem_u32(const void* p) {
    uint32_t a;
    asm("{ .reg .u64 t; cvta.to.shared.u64 t, %1; cvt.u32.u64 %0, t; }" : "=r"(a) : "l"(p));
    return a;
}
#define SWZ128(o) ((o) ^ (((o) >> 3) & 0x70))
static constexpr uint64_t DESC_BASE_SW128 =
    (uint64_t(2) << 61) | (uint64_t(1) << 46) | (uint64_t(64) << 32) | (uint64_t(1) << 16);
#define MK_DESC(a) (DESC_BASE_SW128 | ((uint64_t)((a) >> 4) & 0x3FFF))
#define MMA_IDESC 0x8080490u

#if HAS_TC
__device__ __forceinline__ void mma_f16_ss(uint32_t d, uint64_t a, uint64_t b, uint32_t en) {
    asm volatile(
        "{\n\t.reg .pred p;\n\tsetp.ne.u32 p, %4, 0;\n\t"
        "tcgen05.mma.cta_group::1.kind::f16 [%0], %1, %2, %3, {%5, %5, %5, %5}, p;\n\t}"
        :: "r"(d), "l"(a), "l"(b), "r"(MMA_IDESC), "r"(en), "r"(0u) : "memory");
}
#define TC_ALLOC(sa, n)  asm volatile("tcgen05.alloc.cta_group::1.sync.aligned.shared::cta.b32 [%0], %1;" :: "r"(sa), "r"(n) : "memory")
#define TC_DEALLOC(t, n) asm volatile("tcgen05.dealloc.cta_group::1.sync.aligned.b32 %0, %1;" :: "r"(t), "r"(n))
#define TC_RELINQ()      asm volatile("tcgen05.relinquish_alloc_permit.cta_group::1.sync.aligned;")
#define TC_COMMIT(mb)    asm volatile("tcgen05.commit.cta_group::1.mbarrier::arrive::one.shared::cluster.b64 [%0];" :: "r"(mb) : "memory")
#define TC_FENCE_AFTER() asm volatile("tcgen05.fence::after_thread_sync;" ::: "memory")
#define TC_FENCE_BEFORE() asm volatile("tcgen05.fence::before_thread_sync;" ::: "memory")
#define TC_WAIT_LD()     asm volatile("tcgen05.wait::ld.sync.aligned;" ::: "memory")
#define TC_LD32(r, t) \
    asm volatile("tcgen05.ld.sync.aligned.32x32b.x32.b32 " \
        "{%0,%1,%2,%3,%4,%5,%6,%7,%8,%9,%10,%11,%12,%13,%14,%15," \
        "%16,%17,%18,%19,%20,%21,%22,%23,%24,%25,%26,%27,%28,%29,%30,%31}, [%32];" \
        : "=r"((r)[0]),"=r"((r)[1]),"=r"((r)[2]),"=r"((r)[3]),"=r"((r)[4]),"=r"((r)[5]),"=r"((r)[6]),"=r"((r)[7]), \
          "=r"((r)[8]),"=r"((r)[9]),"=r"((r)[10]),"=r"((r)[11]),"=r"((r)[12]),"=r"((r)[13]),"=r"((r)[14]),"=r"((r)[15]), \
          "=r"((r)[16]),"=r"((r)[17]),"=r"((r)[18]),"=r"((r)[19]),"=r"((r)[20]),"=r"((r)[21]),"=r"((r)[22]),"=r"((r)[23]), \
          "=r"((r)[24]),"=r"((r)[25]),"=r"((r)[26]),"=r"((r)[27]),"=r"((r)[28]),"=r"((r)[29]),"=r"((r)[30]),"=r"((r)[31]) \
        : "r"(t))
#endif

#define MBAR_INIT(mb, n) asm volatile("mbarrier.init.shared.b64 [%0], %1;" :: "r"(mb), "r"(n) : "memory")
#define MBAR_INVAL(mb)   asm volatile("mbarrier.inval.shared.b64 [%0];" :: "r"(mb) : "memory")
#define MBAR_WAIT(mb, ph) do { \
    uint32_t _m = (mb), _p = (ph), _d; \
    asm volatile("{\n\t.reg .pred p;\n\tmbarrier.try_wait.parity.acquire.cta.shared::cta.b64 p, [%1], %2;\n\tselp.b32 %0, 1, 0, p;\n\t}" \
        : "=r"(_d) : "r"(_m), "r"(_p) : "memory"); \
    if (!_d) { \
        asm volatile("{\n\t.reg .pred P1;\n\tWL_%=:\n\tmbarrier.try_wait.parity.acquire.cta.shared::cta.b64 P1, [%0], %1, 0x989680;\n\t@P1 bra.uni WD_%=;\n\tbra.uni WL_%=;\n\tWD_%=:\n\t}" \
            :: "r"(_m), "r"(_p) : "memory"); \
    } } while (0)

// conv1t smem layout (R14)
#define SM_TM   0
#define SM_BAR0 8
#define SM_BAR1 16
#define SM_BH   1024
#define SM_BL   (SM_BH + 28672)
#define SM_A    (SM_BL + 28672)          // 2 bufs x (16KB hi + 16KB lo)
#define SM_BIAS (SM_A + 65536)
#define SM_C1_TOTAL (SM_BIAS + 128 + 1024)
// conv2t smem layout (R14)
#define SM2_BH   1024
#define SM2_BL   (SM2_BH + 16384)
#define SM2_A    (SM2_BL + 16384)
#define SM2_BIAS (SM2_A + 65536)
#define SM_C2_TOTAL (SM2_BIAS + 128 + 1024)

// ---------------- prep ----------------
__global__ __launch_bounds__(256) void k_prep(const float* __restrict__ W1,
                                              const float* __restrict__ W2,
                                              const float* __restrict__ W_up)
{
    int gt = blockIdx.x * 256 + threadIdx.x;
    int stride = gridDim.x * 256;
    if (gt < NB * 32) { g_s1[gt] = 0.f; g_q1[gt] = 0.f; g_s2[gt] = 0.f; g_q2[gt] = 0.f; }
    for (int i = gt; i < 448 * 32; i += stride) {
        int k = i >> 5, c = i & 31;
        g_W1t[i] = W1[c * 448 + k];
    }
    for (int i = gt; i < 224 * 32; i += stride) {
        int k = i >> 5, c = i & 31;
        g_W2t[i] = W2[c * 224 + k];
    }
    for (int i = gt; i < 7 * 64 * 32; i += stride) {
        int rg = i >> 11, rem = i & 2047;
        int k = rem >> 5, c = rem & 31;
        g_Wut[i] = W_up[(rg * 32 + c) * 64 + k];
    }
    for (int i = gt; i < 7 * 2048; i += stride) {
        int j = i >> 11, rem = i & 2047;
        int r = rem >> 6, kk = rem & 63;
        float v = W1[r * 448 + j * 64 + kk];
        __nv_bfloat16 h = __float2bfloat16(v);
        __nv_bfloat16 l = __float2bfloat16(v - __bfloat162float(h));
        uint32_t sw = SWZ128((uint32_t)(r * 128 + kk * 2));
        g_W1h[j * 2048 + (sw >> 1)] = h;
        g_W1l[j * 2048 + (sw >> 1)] = l;
    }
    for (int i = gt; i < 4 * 2048; i += stride) {
        int j = i >> 11, rem = i & 2047;
        int r = rem >> 6, kk = rem & 63;
        int ksrc = j * 64 + kk;
        float v = (ksrc < 224) ? W2[r * 224 + ksrc] : 0.f;
        __nv_bfloat16 h = __float2bfloat16(v);
        __nv_bfloat16 l = __float2bfloat16(v - __bfloat162float(h));
        uint32_t sw = SWZ128((uint32_t)(r * 128 + kk * 2));
        g_W2h[j * 2048 + (sw >> 1)] = h;
        g_W2l[j * 2048 + (sw >> 1)] = l;
    }
}

// ---------------- upconv GEMM (R5) ----------------
__global__ __launch_bounds__(256) void k_upgemm(const float* __restrict__ x1,
                                                const float* __restrict__ b_up)
{
    float* Wt = smem;
    float* bs = Wt + 7 * 64 * 32;
    float* mblk = bs + 224;
    float* sblk = mblk + 8 * 32 * 65;
    int tid = threadIdx.x, b = blockIdx.y;

    for (int i = tid; i < 7 * 64 * 32; i += 256) Wt[i] = g_Wut[i];
    for (int i = tid; i < 224; i += 256) bs[i] = b_up[i];
    __syncthreads();

    int warp = tid >> 5, lane = tid & 31;
    int tb = (blockIdx.x * 8 + warp) * 32;
    if (tb >= V1) return;
    int nvalid = V1 - tb; if (nvalid > 32) nvalid = 32;
    float* m = mblk + warp * 32 * 65;
    float* st = sblk + warp * 32 * 33;
    const float* x1b = x1 + (size_t)b * 64 * V1;
    float* rb = g_raw + (size_t)b * V1 * 224;

    {
        int v = tb + lane;
        bool ok = (lane < nvalid);
#pragma unroll 8
        for (int c = 0; c < 64; ++c)
            m[lane * 65 + c] = ok ? x1b[(size_t)c * V1 + v] : 0.f;
    }
    __syncwarp();

    const float* mp = m + lane * 65;
    for (int rg = 0; rg < 7; ++rg) {
        float acc[32];
#pragma unroll
        for (int q = 0; q < 8; ++q) {
            float4 b4 = *(const float4*)(bs + rg * 32 + 4 * q);
            acc[4 * q] = b4.x; acc[4 * q + 1] = b4.y;
            acc[4 * q + 2] = b4.z; acc[4 * q + 3] = b4.w;
        }
        const float* wp = Wt + rg * 64 * 32;
#pragma unroll 8
        for (int k = 0; k < 64; ++k) {
            float xm = mp[k];
            const float* w = wp + k * 32;
#pragma unroll
            for (int q = 0; q < 8; ++q) {
                float4 w4 = *(const float4*)(w + 4 * q);
                acc[4 * q]     = fmaf(xm, w4.x, acc[4 * q]);
                acc[4 * q + 1] = fmaf(xm, w4.y, acc[4 * q + 1]);
                acc[4 * q + 2] = fmaf(xm, w4.z, acc[4 * q + 2]);
                acc[4 * q + 3] = fmaf(xm, w4.w, acc[4 * q + 3]);
            }
        }
#pragma unroll
        for (int c = 0; c < 32; ++c) st[lane * 33 + c] = acc[c];
        __syncwarp();
#pragma unroll
        for (int r = 0; r < 8; ++r) {
            int v = 4 * r + (lane >> 3);
            int c = 4 * (lane & 7);
            if (v < nvalid) {
                float4 o = make_float4(st[v * 33 + c], st[v * 33 + c + 1],
                                       st[v * 33 + c + 2], st[v * 33 + c + 3]);
                *(float4*)(rb + (size_t)(tb + v) * 224 + rg * 32 + c) = o;
            }
        }
        __syncwarp();
    }
}

// ---------------- scatter + skip concat (R5) ----------------
__global__ __launch_bounds__(256) void k_scatter(const float* __restrict__ x2,
                                                 const int* __restrict__ top,
                                                 const int* __restrict__ down)
{
    int b = blockIdx.y;
    int v0 = blockIdx.x * 256;
    const float* fb = g_raw + (size_t)b * V1 * 224;
    float* yb = g_y + (size_t)b * V2 * 64;
    int tid = threadIdx.x;
    for (int pass = 0; pass < 8; ++pass) {
        int vl = pass * 32 + (tid >> 3);
        int v = v0 + vl;
        int c0 = 4 * (tid & 7);
        if (v < V1) {
            int t = top[v];
            float4 f = *(const float4*)(fb + (size_t)t * 32 + c0);
            *(float4*)(yb + (size_t)v * 64 + c0) = f;
        } else if (v < V2) {
            int n = v - V1;
            int r = down[2 * n + (c0 >= 16 ? 1 : 0)];
            int base = (2 * c0) & 31;
            float4 f0 = *(const float4*)(fb + (size_t)r * 32 + base);
            float4 f1 = *(const float4*)(fb + (size_t)r * 32 + base + 4);
            float4 o;
            o.x = 0.5f * (f0.x + f0.y); o.y = 0.5f * (f0.z + f0.w);
            o.z = 0.5f * (f1.x + f1.y); o.w = 0.5f * (f1.z + f1.w);
            *(float4*)(yb + (size_t)v * 64 + c0) = o;
        }
    }
    const float* x2b = x2 + (size_t)b * 32 * V2;
    for (int i = tid; i < 256 * 32; i += 256) {
        int c = i & 31, vl = i >> 5;
        int v = v0 + vl;
        if (v < V2) yb[(size_t)v * 64 + 32 + c] = x2b[(size_t)c * V2 + v];
    }
}

#define C1_NTILES ((V2 + 127) / 128)
#define C1_TOTAL_TILES (C1_NTILES * NB)

// ---------------- conv1 (tensor): persistent R14 + cross-tile prefetch ----------------
__global__ __launch_bounds__(512)
void k_conv1t(const int* __restrict__ neigh, const float* __restrict__ b1)
{
#if HAS_TC
    char* sb0 = (char*)smem;
    uint32_t su0 = smem_u32(sb0);
    uint32_t pad = ((su0 + 1023u) & ~1023u) - su0;
    char* sb = sb0 + pad;
    uint32_t su = su0 + pad;

    int tid = threadIdx.x, wid = tid >> 5, lane = tid & 31;

    if (wid == 0) { TC_ALLOC(su + SM_TM, 128); TC_RELINQ(); }
    if (tid == 128) { MBAR_INIT(su + SM_BAR0, 1); MBAR_INIT(su + SM_BAR1, 1); }

    {
        const uint4* srcH = (const uint4*)g_W1h;
        const uint4* srcL = (const uint4*)g_W1l;
        uint4* dstH = (uint4*)(sb + SM_BH);
        uint4* dstL = (uint4*)(sb + SM_BL);
        for (int i = tid; i < 1792; i += 512) { dstH[i] = srcH[i]; dstL[i] = srcL[i]; }
    }
    if (tid < 32) ((float*)(sb + SM_BIAS))[tid] = b1[tid];
    __syncthreads();

    uint32_t tmem_base;
    asm volatile("ld.shared.b32 %0, [%1];" : "=r"(tmem_base) : "r"(su + SM_TM));

    int row = tid >> 2;
    int quarter = tid & 3;
    int par0 = 0, par1 = 0;
    uint32_t swoff0 = SWZ128((uint32_t)(row * 128 + (quarter * 16 + 0) * 2));
    uint32_t swoff1 = SWZ128((uint32_t)(row * 128 + (quarter * 16 + 8) * 2));

    // cross-tile state: indices + chunk0 of the upcoming tile
    int nbs[7];
    float4 rcur[4];
    {
        int t0 = blockIdx.x;
        if (t0 < C1_TOTAL_TILES) {
            int b0 = t0 / C1_NTILES;
            int tb0 = (t0 % C1_NTILES) * 128;
            int nv0 = V2 - tb0; if (nv0 > 128) nv0 = 128;
            bool rv0 = (row < nv0);
            const float* yb0 = g_y + (size_t)b0 * V2 * 64;
            const int* np = neigh + (size_t)(tb0 + (rv0 ? row : 0)) * 7;
#pragma unroll
            for (int q = 0; q < 7; ++q) nbs[q] = np[q];
            const float* src = yb0 + (size_t)nbs[0] * 64 + quarter * 16;
#pragma unroll
            for (int g = 0; g < 4; ++g)
                rcur[g] = rv0 ? *(const float4*)(src + 4 * g) : make_float4(0.f, 0.f, 0.f, 0.f);
        }
    }

    for (int t = blockIdx.x; t < C1_TOTAL_TILES; t += gridDim.x) {
        int b = t / C1_NTILES;
        int tb = (t % C1_NTILES) * 128;
        int nvalid = V2 - tb; if (nvalid > 128) nvalid = 128;
        const float* yb = g_y + (size_t)b * V2 * 64;
        bool rv = (row < nvalid);

        float4 rnxt[4];
        for (int j = 0; j < 7; ++j) {
            int buf = j & 1;
            if (j < 6) {
                const float* src = yb + (size_t)nbs[j + 1] * 64 + quarter * 16;
#pragma unroll
                for (int g = 0; g < 4; ++g)
                    rnxt[g] = rv ? *(const float4*)(src + 4 * g) : make_float4(0.f, 0.f, 0.f, 0.f);
            } else {
                // j == 6: nbs dead -> prefetch NEXT tile's indices + chunk0
                int tn = t + gridDim.x;
                if (tn < C1_TOTAL_TILES) {
                    int bn = tn / C1_NTILES;
                    int tbn = (tn % C1_NTILES) * 128;
                    int nvn = V2 - tbn; if (nvn > 128) nvn = 128;
                    bool rvn = (row < nvn);
                    const float* ybn = g_y + (size_t)bn * V2 * 64;
                    const int* np = neigh + (size_t)(tbn + (rvn ? row : 0)) * 7;
#pragma unroll
                    for (int q = 0; q < 7; ++q) nbs[q] = np[q];
                    const float* src = ybn + (size_t)nbs[0] * 64 + quarter * 16;
#pragma unroll
                    for (int g = 0; g < 4; ++g)
                        rnxt[g] = rvn ? *(const float4*)(src + 4 * g) : make_float4(0.f, 0.f, 0.f, 0.f);
                }
            }
            if (j >= 2) {
                if (buf == 0) { MBAR_WAIT(su + SM_BAR0, par0); par0 ^= 1; }
                else          { MBAR_WAIT(su + SM_BAR1, par1); par1 ^= 1; }
            }
            // packed bf16 split conversion + STS
            {
                char* Ah = sb + SM_A + buf * 32768;
                char* Al = Ah + 16384;
#pragma unroll
                for (int st = 0; st < 2; ++st) {
                    float4 fa = rcur[2 * st];
                    float4 fb2 = rcur[2 * st + 1];
                    float fv[8] = {fa.x, fa.y, fa.z, fa.w, fb2.x, fb2.y, fb2.z, fb2.w};
                    uint32_t hw[4], lw[4];
#pragma unroll
                    for (int p = 0; p < 4; ++p) {
                        float f0 = fv[2 * p], f1 = fv[2 * p + 1];
                        uint32_t h;
                        asm("cvt.rn.bf16x2.f32 %0, %1, %2;" : "=r"(h) : "f"(f1), "f"(f0));
                        float h0 = __uint_as_float(h << 16);
                        float h1 = __uint_as_float(h & 0xffff0000u);
                        uint32_t l;
                        asm("cvt.rn.bf16x2.f32 %0, %1, %2;" : "=r"(l) : "f"(f1 - h1), "f"(f0 - h0));
                        hw[p] = h; lw[p] = l;
                    }
                    uint32_t off = st ? swoff1 : swoff0;
                    *(uint4*)(Ah + off) = make_uint4(hw[0], hw[1], hw[2], hw[3]);
                    *(uint4*)(Al + off) = make_uint4(lw[0], lw[1], lw[2], lw[3]);
                }
            }
            __syncthreads();
            if (tid == 0) {
                asm volatile("fence.proxy.async.shared::cta;" ::: "memory");
                uint64_t ah = MK_DESC(su + SM_A + buf * 32768);
                uint64_t al = MK_DESC(su + SM_A + buf * 32768 + 16384);
                uint64_t bh = MK_DESC(su + SM_BH + j * 4096);
                uint64_t bl = MK_DESC(su + SM_BL + j * 4096);
#pragma unroll
                for (int s = 0; s < 4; ++s)
                    mma_f16_ss(tmem_base, ah + 2 * s, bh + 2 * s, !(j == 0 && s == 0));
#pragma unroll
                for (int s = 0; s < 4; ++s)
                    mma_f16_ss(tmem_base, al + 2 * s, bh + 2 * s, 1u);
#pragma unroll
                for (int s = 0; s < 4; ++s)
                    mma_f16_ss(tmem_base, ah + 2 * s, bl + 2 * s, 1u);
                TC_COMMIT(su + (buf ? SM_BAR1 : SM_BAR0));
            }
#pragma unroll
            for (int g = 0; g < 4; ++g) rcur[g] = rnxt[g];
        }
        // tile-end drain with parity flips (persistent kernel)
        MBAR_WAIT(su + SM_BAR1, par1); par1 ^= 1;
        MBAR_WAIT(su + SM_BAR0, par0); par0 ^= 1;
        TC_FENCE_AFTER();

        if (tid < 128) {
            uint32_t d_regs[32];
            TC_LD32(d_regs, tmem_base);
            TC_WAIT_LD();
            TC_FENCE_BEFORE();
            const float* bias = (const float*)(sb + SM_BIAS);
            int myrow = wid * 32 + lane;
            bool valid = (myrow < nvalid);
            float vals[32];
#pragma unroll
            for (int c = 0; c < 32; ++c)
                vals[c] = valid ? (__uint_as_float(d_regs[c]) + bias[c]) : 0.f;
            if (valid) {
                float* d = g_h1 + (size_t)b * V2 * 32 + (size_t)(tb + myrow) * 32;
#pragma unroll
                for (int qq = 0; qq < 8; ++qq)
                    *(float4*)(d + 4 * qq) = make_float4(vals[4 * qq], vals[4 * qq + 1],
                                                         vals[4 * qq + 2], vals[4 * qq + 3]);
            }
            float qv[32];
#pragma unroll
            for (int c = 0; c < 32; ++c) qv[c] = vals[c] * vals[c];
#pragma unroll
            for (int d = 1; d < 32; d <<= 1) {
#pragma unroll
                for (int c = 0; c < 32; ++c) {
                    vals[c] += __shfl_xor_sync(0xffffffffu, vals[c], d);
                    qv[c]   += __shfl_xor_sync(0xffffffffu, qv[c], d);
                }
            }
            atomicAdd(&g_s1[b * 32 + lane], vals[lane]);
            atomicAdd(&g_q1[b * 32 + lane], qv[lane]);
        }
        __syncthreads();
    }

    if (tid == 128) { MBAR_INVAL(su + SM_BAR0); MBAR_INVAL(su + SM_BAR1); }
    __syncthreads();
    if (wid == 0) TC_DEALLOC(tmem_base, 128);
#endif
}

// ---------------- conv2 (tensor): persistent R14 (K pad 256, 4 rounds) + cross-tile prefetch ----------------
__global__ __launch_bounds__(512)
void k_conv2t(const int* __restrict__ neigh, const float* __restrict__ b2)
{
#if HAS_TC
    char* sb0 = (char*)smem;
    uint32_t su0 = smem_u32(sb0);
    uint32_t pad = ((su0 + 1023u) & ~1023u) - su0;
    char* sb = sb0 + pad;
    uint32_t su = su0 + pad;

    int tid = threadIdx.x, wid = tid >> 5, lane = tid & 31;

    if (wid == 0) { TC_ALLOC(su + SM_TM, 128); TC_RELINQ(); }
    if (tid == 128) { MBAR_INIT(su + SM_BAR0, 1); MBAR_INIT(su + SM_BAR1, 1); }

    {
        const uint4* srcH = (const uint4*)g_W2h;
        const uint4* srcL = (const uint4*)g_W2l;
        uint4* dstH = (uint4*)(sb + SM2_BH);
        uint4* dstL = (uint4*)(sb + SM2_BL);
        for (int i = tid; i < 1024; i += 512) { dstH[i] = srcH[i]; dstL[i] = srcL[i]; }
    }
    if (tid < 32) ((float*)(sb + SM2_BIAS))[tid] = b2[tid];
    __syncthreads();

    uint32_t tmem_base;
    asm volatile("ld.shared.b32 %0, [%1];" : "=r"(tmem_base) : "r"(su + SM_TM));

    int row = tid >> 2;
    int quarter = tid & 3;
    int nbsel = quarter >> 1;
    int coff = (quarter & 1) * 16;
    int par0 = 0, par1 = 0;
    uint32_t swoff0 = SWZ128((uint32_t)(row * 128 + (quarter * 16 + 0) * 2));
    uint32_t swoff1 = SWZ128((uint32_t)(row * 128 + (quarter * 16 + 8) * 2));

    // cross-tile state
    int nbs[7];
    float4 rcur[4];
    {
        int t0 = blockIdx.x;
        if (t0 < C1_TOTAL_TILES) {
            int b0 = t0 / C1_NTILES;
            int tb0 = (t0 % C1_NTILES) * 128;
            int nv0 = V2 - tb0; if (nv0 > 128) nv0 = 128;
            bool rv0 = (row < nv0);
            const float* h1b0 = g_h1 + (size_t)b0 * V2 * 32;
            const int* np = neigh + (size_t)(tb0 + (rv0 ? row : 0)) * 7;
#pragma unroll
            for (int q = 0; q < 7; ++q) nbs[q] = np[q];
            const float* src = h1b0 + (size_t)nbs[nbsel] * 32 + coff;
#pragma unroll
            for (int g = 0; g < 4; ++g)
                rcur[g] = rv0 ? *(const float4*)(src + 4 * g) : make_float4(0.f, 0.f, 0.f, 0.f);
        }
    }

    for (int t = blockIdx.x; t < C1_TOTAL_TILES; t += gridDim.x) {
        int b = t / C1_NTILES;
        int tb = (t % C1_NTILES) * 128;
        int nvalid = V2 - tb; if (nvalid > 128) nvalid = 128;
        const float* h1b = g_h1 + (size_t)b * V2 * 32;
        bool rv = (row < nvalid);

        float4 sc4[4], sh4[4];
#pragma unroll
        for (int g = 0; g < 4; ++g) {
            sc4[g] = *(const float4*)(g_sc1 + b * 32 + coff + 4 * g);
            sh4[g] = *(const float4*)(g_sh1 + b * 32 + coff + 4 * g);
        }

        float4 rnxt[4];
        for (int j = 0; j < 4; ++j) {
            int buf = j & 1;
            if (j < 3) {
                int nn = 2 * (j + 1) + nbsel;
                int nb = nbs[nn < 7 ? nn : 6];   // pad round dup; W pad cols are zero
                const float* src = h1b + (size_t)nb * 32 + coff;
#pragma unroll
                for (int g = 0; g < 4; ++g)
                    rnxt[g] = rv ? *(const float4*)(src + 4 * g) : make_float4(0.f, 0.f, 0.f, 0.f);
            } else {
                // j == 3: nbs dead -> prefetch NEXT tile's indices + chunk0
                int tn = t + gridDim.x;
                if (tn < C1_TOTAL_TILES) {
                    int bn = tn / C1_NTILES;
                    int tbn = (tn % C1_NTILES) * 128;
                    int nvn = V2 - tbn; if (nvn > 128) nvn = 128;
                    bool rvn = (row < nvn);
                    const float* h1bn = g_h1 + (size_t)bn * V2 * 32;
                    const int* np = neigh + (size_t)(tbn + (rvn ? row : 0)) * 7;
#pragma unroll
                    for (int q = 0; q < 7; ++q) nbs[q] = np[q];
                    const float* src = h1bn + (size_t)nbs[nbsel] * 32 + coff;
#pragma unroll
                    for (int g = 0; g < 4; ++g)
                        rnxt[g] = rvn ? *(const float4*)(src + 4 * g) : make_float4(0.f, 0.f, 0.f, 0.f);
                }
            }
            if (j >= 2) {
                if (buf == 0) { MBAR_WAIT(su + SM_BAR0, par0); par0 ^= 1; }
                else          { MBAR_WAIT(su + SM_BAR1, par1); par1 ^= 1; }
            }
            // fold BN1+LReLU (current tile's sc/sh), packed bf16 split, STS
            {
                char* Ah = sb + SM2_A + buf * 32768;
                char* Al = Ah + 16384;
#pragma unroll
                for (int st = 0; st < 2; ++st) {
                    float fv[8];
#pragma unroll
                    for (int g2 = 0; g2 < 2; ++g2) {
                        int gi = 2 * st + g2;
                        float4 f = rcur[gi];
                        float4 sc = sc4[gi], sh = sh4[gi];
                        f.x = fmaf(f.x, sc.x, sh.x); f.x = f.x >= 0.f ? f.x : SLOPE * f.x;
                        f.y = fmaf(f.y, sc.y, sh.y); f.y = f.y >= 0.f ? f.y : SLOPE * f.y;
                        f.z = fmaf(f.z, sc.z, sh.z); f.z = f.z >= 0.f ? f.z : SLOPE * f.z;
                        f.w = fmaf(f.w, sc.w, sh.w); f.w = f.w >= 0.f ? f.w : SLOPE * f.w;
                        fv[4 * g2 + 0] = f.x; fv[4 * g2 + 1] = f.y;
                        fv[4 * g2 + 2] = f.z; fv[4 * g2 + 3] = f.w;
                    }
                    uint32_t hw[4], lw[4];
#pragma unroll
                    for (int p = 0; p < 4; ++p) {
                        float f0 = fv[2 * p], f1 = fv[2 * p + 1];
                        uint32_t h;
                        asm("cvt.rn.bf16x2.f32 %0, %1, %2;" : "=r"(h) : "f"(f1), "f"(f0));
                        float h0 = __uint_as_float(h << 16);
                        float h1f = __uint_as_float(h & 0xffff0000u);
                        uint32_t l;
                        asm("cvt.rn.bf16x2.f32 %0, %1, %2;" : "=r"(l) : "f"(f1 - h1f), "f"(f0 - h0));
                        hw[p] = h; lw[p] = l;
                    }
                    uint32_t off = st ? swoff1 : swoff0;
                    *(uint4*)(Ah + off) = make_uint4(hw[0], hw[1], hw[2], hw[3]);
                    *(uint4*)(Al + off) = make_uint4(lw[0], lw[1], lw[2], lw[3]);
                }
            }
            __syncthreads();
            if (tid == 0) {
                asm volatile("fence.proxy.async.shared::cta;" ::: "memory");
                uint64_t ah = MK_DESC(su + SM2_A + buf * 32768);
                uint64_t al = MK_DESC(su + SM2_A + buf * 32768 + 16384);
                uint64_t bh = MK_DESC(su + SM2_BH + j * 4096);
                uint64_t bl = MK_DESC(su + SM2_BL + j * 4096);
#pragma unroll
                for (int s = 0; s < 4; ++s)
                    mma_f16_ss(tmem_base, ah + 2 * s, bh + 2 * s, !(j == 0 && s == 0));
#pragma unroll
                for (int s = 0; s < 4; ++s)
                    mma_f16_ss(tmem_base, al + 2 * s, bh + 2 * s, 1u);
#pragma unroll
                for (int s = 0; s < 4; ++s)
                    mma_f16_ss(tmem_base, ah + 2 * s, bl + 2 * s, 1u);
                TC_COMMIT(su + (buf ? SM_BAR1 : SM_BAR0));
            }
#pragma unroll
            for (int g = 0; g < 4; ++g) rcur[g] = rnxt[g];
        }
        // tile-end drain with parity flips
        MBAR_WAIT(su + SM_BAR1, par1); par1 ^= 1;
        MBAR_WAIT(su + SM_BAR0, par0); par0 ^= 1;
        TC_FENCE_AFTER();

        if (tid < 128) {
            uint32_t d_regs[32];
            TC_LD32(d_regs, tmem_base);
            TC_WAIT_LD();
            TC_FENCE_BEFORE();
            const float* bias = (const float*)(sb + SM2_BIAS);
            int myrow = wid * 32 + lane;
            bool valid = (myrow < nvalid);
            float vals[32];
#pragma unroll
            for (int c = 0; c < 32; ++c)
                vals[c] = valid ? (__uint_as_float(d_regs[c]) + bias[c]) : 0.f;
            if (valid) {
                float* d = g_h2 + (size_t)b * V2 * 32 + (size_t)(tb + myrow) * 32;
#pragma unroll
                for (int qq = 0; qq < 8; ++qq)
                    *(float4*)(d + 4 * qq) = make_float4(vals[4 * qq], vals[4 * qq + 1],
                                                         vals[4 * qq + 2], vals[4 * qq + 3]);
            }
            float qv[32];
#pragma unroll
            for (int c = 0; c < 32; ++c) qv[c] = vals[c] * vals[c];
#pragma unroll
            for (int d = 1; d < 32; d <<= 1) {
#pragma unroll
                for (int c = 0; c < 32; ++c) {
                    vals[c] += __shfl_xor_sync(0xffffffffu, vals[c], d);
                    qv[c]   += __shfl_xor_sync(0xffffffffu, qv[c], d);
                }
            }
            atomicAdd(&g_s2[b * 32 + lane], vals[lane]);
            atomicAdd(&g_q2[b * 32 + lane], qv[lane]);
        }
        __syncthreads();
    }

    if (tid == 128) { MBAR_INVAL(su + SM_BAR0); MBAR_INVAL(su + SM_BAR1); }
    __syncthreads();
    if (wid == 0) TC_DEALLOC(tmem_base, 128);
#endif
}

// ---------------- FFMA fallbacks (body only without tcgen05) ----------------
__global__ __launch_bounds__(512) void k_conv1f(const int* __restrict__ neigh,
                                                const float* __restrict__ b1)
{
#if !HAS_TC
    float* Wt = smem;
    float* mblk = Wt + 448 * 32;
    int* nblk = (int*)(mblk + 16 * 2112);
    int tid = threadIdx.x, b = blockIdx.y;
    for (int i = tid; i < 448 * 32; i += 512) Wt[i] = g_W1t[i];
    __syncthreads();
    int warp = tid >> 5, lane = tid & 31;
    int tb = (blockIdx.x * 16 + warp) * 32;
    if (tb >= V2) return;
    int nvalid = V2 - tb; if (nvalid > 32) nvalid = 32;
    float* mw = mblk + warp * 2112;
    int* nidxT = nblk + warp * 224;
    const float* yb = g_y + (size_t)b * V2 * 64;
    float* hb = g_h1 + (size_t)b * V2 * 32;
    {
        int vv = tb + (lane < nvalid ? lane : 0);
#pragma unroll
        for (int q = 0; q < 7; ++q)
            nidxT[q * 32 + lane] = neigh[(size_t)vv * 7 + q];
    }
    __syncwarp();
    float acc[32];
#pragma unroll
    for (int q = 0; q < 8; ++q) {
        float4 b4 = *(const float4*)(b1 + 4 * q);
        acc[4 * q] = b4.x; acc[4 * q + 1] = b4.y;
        acc[4 * q + 2] = b4.z; acc[4 * q + 3] = b4.w;
    }
    int rsel = lane >> 3;
    int cg = 4 * (lane & 7);
    const float* mp0 = mw + lane * 33;
    float4 pf[8];
#pragma unroll
    for (int r = 0; r < 8; ++r) {
        int nb = nidxT[4 * r + rsel];
        pf[r] = *(const float4*)(yb + (size_t)nb * 64 + cg);
    }
#pragma unroll
    for (int r = 0; r < 8; ++r) {
        int v = 4 * r + rsel;
        float* d = mw + v * 33 + cg;
        d[0] = pf[r].x; d[1] = pf[r].y; d[2] = pf[r].z; d[3] = pf[r].w;
    }
#pragma unroll
    for (int r = 0; r < 8; ++r) {
        int nb = nidxT[4 * r + rsel];
        pf[r] = *(const float4*)(yb + (size_t)nb * 64 + 32 + cg);
    }
    __syncwarp();
    for (int ch = 0; ch < 14; ++ch) {
        const float* mp = mp0 + (ch & 1) * 1056;
        const float* wp = Wt + ch * 32 * 32;
#pragma unroll 8
        for (int kk = 0; kk < 32; ++kk) {
            float xm = mp[kk];
            const float* w = wp + kk * 32;
#pragma unroll
            for (int q = 0; q < 8; ++q) {
                float4 w4 = *(const float4*)(w + 4 * q);
                acc[4 * q]     = fmaf(xm, w4.x, acc[4 * q]);
                acc[4 * q + 1] = fmaf(xm, w4.y, acc[4 * q + 1]);
                acc[4 * q + 2] = fmaf(xm, w4.z, acc[4 * q + 2]);
                acc[4 * q + 3] = fmaf(xm, w4.w, acc[4 * q + 3]);
            }
        }
        if (ch < 13) {
            float* dbuf = mw + ((ch + 1) & 1) * 1056;
#pragma unroll
            for (int r = 0; r < 8; ++r) {
                int v = 4 * r + rsel;
                float* d = dbuf + v * 33 + cg;
                d[0] = pf[r].x; d[1] = pf[r].y; d[2] = pf[r].z; d[3] = pf[r].w;
            }
            if (ch < 12) {
                int nc = ch + 2;
                int j = nc >> 1;
                int bc = ((nc & 1) << 5) + cg;
#pragma unroll
                for (int r = 0; r < 8; ++r) {
                    int nb = nidxT[j * 32 + 4 * r + rsel];
                    pf[r] = *(const float4*)(yb + (size_t)nb * 64 + bc);
                }
            }
            __syncwarp();
        }
    }
    __syncwarp();
    if (lane >= nvalid) {
#pragma unroll
        for (int c = 0; c < 32; ++c) acc[c] = 0.f;
    }
    float* st = mw;
#pragma unroll
    for (int c = 0; c < 32; ++c) st[lane * 33 + c] = acc[c];
    __syncwarp();
#pragma unroll
    for (int r = 0; r < 8; ++r) {
        int v = 4 * r + rsel;
        if (v < nvalid) {
            float4 o = make_float4(st[v * 33 + cg], st[v * 33 + cg + 1],
                                   st[v * 33 + cg + 2], st[v * 33 + cg + 3]);
            *(float4*)(hb + (size_t)(tb + v) * 32 + cg) = o;
        }
    }
    float s = 0.f, q = 0.f;
#pragma unroll 8
    for (int v = 0; v < 32; ++v) {
        float x = st[v * 33 + lane];
        s += x;
        q = fmaf(x, x, q);
    }
    atomicAdd(&g_s1[b * 32 + lane], s);
    atomicAdd(&g_q1[b * 32 + lane], q);
#endif
}

__global__ __launch_bounds__(512) void k_conv2f(const int* __restrict__ neigh,
                                                const float* __restrict__ b2)
{
#if !HAS_TC
    float* Wt = smem;
    float* mblk = Wt + 224 * 32;
    int* nblk = (int*)(mblk + 16 * 2112);
    int tid = threadIdx.x, b = blockIdx.y;
    for (int i = tid; i < 224 * 32; i += 512) Wt[i] = g_W2t[i];
    __syncthreads();
    int warp = tid >> 5, lane = tid & 31;
    int tb = (blockIdx.x * 16 + warp) * 32;
    if (tb >= V2) return;
    int nvalid = V2 - tb; if (nvalid > 32) nvalid = 32;
    float* mw = mblk + warp * 2112;
    int* nidxT = nblk + warp * 224;
    const float* h1b = g_h1 + (size_t)b * V2 * 32;
    float* h2b = g_h2 + (size_t)b * V2 * 32;
    {
        int vv = tb + (lane < nvalid ? lane : 0);
#pragma unroll
        for (int q = 0; q < 7; ++q)
            nidxT[q * 32 + lane] = neigh[(size_t)vv * 7 + q];
    }
    __syncwarp();
    int rsel = lane >> 3;
    int cg = 4 * (lane & 7);
    float4 sc4 = *(const float4*)(g_sc1 + b * 32 + cg);
    float4 sh4 = *(const float4*)(g_sh1 + b * 32 + cg);
    float acc[32];
#pragma unroll
    for (int q = 0; q < 8; ++q) {
        float4 b4 = *(const float4*)(b2 + 4 * q);
        acc[4 * q] = b4.x; acc[4 * q + 1] = b4.y;
        acc[4 * q + 2] = b4.z; acc[4 * q + 3] = b4.w;
    }
    const float* mp0 = mw + lane * 33;
    float4 pf[8];
#pragma unroll
    for (int r = 0; r < 8; ++r) {
        int nb = nidxT[4 * r + rsel];
        pf[r] = *(const float4*)(h1b + (size_t)nb * 32 + cg);
    }
#pragma unroll
    for (int r = 0; r < 8; ++r) {
        int v = 4 * r + rsel;
        float4 f = pf[r];
        f.x = fmaf(f.x, sc4.x, sh4.x); f.x = f.x >= 0.f ? f.x : SLOPE * f.x;
        f.y = fmaf(f.y, sc4.y, sh4.y); f.y = f.y >= 0.f ? f.y : SLOPE * f.y;
        f.z = fmaf(f.z, sc4.z, sh4.z); f.z = f.z >= 0.f ? f.z : SLOPE * f.z;
        f.w = fmaf(f.w, sc4.w, sh4.w); f.w = f.w >= 0.f ? f.w : SLOPE * f.w;
        float* d = mw + v * 33 + cg;
        d[0] = f.x; d[1] = f.y; d[2] = f.z; d[3] = f.w;
    }
#pragma unroll
    for (int r = 0; r < 8; ++r) {
        int nb = nidxT[32 + 4 * r + rsel];
        pf[r] = *(const float4*)(h1b + (size_t)nb * 32 + cg);
    }
    __syncwarp();
    for (int ch = 0; ch < 7; ++ch) {
        const float* mp = mp0 + (ch & 1) * 1056;
        const float* wp = Wt + ch * 32 * 32;
#pragma unroll 8
        for (int kk = 0; kk < 32; ++kk) {
            float xm = mp[kk];
            const float* w = wp + kk * 32;
#pragma unroll
            for (int q = 0; q < 8; ++q) {
                float4 w4 = *(const float4*)(w + 4 * q);
                acc[4 * q]     = fmaf(xm, w4.x, acc[4 * q]);
                acc[4 * q + 1] = fmaf(xm, w4.y, acc[4 * q + 1]);
                acc[4 * q + 2] = fmaf(xm, w4.z, acc[4 * q + 2]);
                acc[4 * q + 3] = fmaf(xm, w4.w, acc[4 * q + 3]);
            }
        }
        if (ch < 6) {
            float* dbuf = mw + ((ch + 1) & 1) * 1056;
#pragma unroll
            for (int r = 0; r < 8; ++r) {
                int v = 4 * r + rsel;
                float4 f = pf[r];
                f.x = fmaf(f.x, sc4.x, sh4.x); f.x = f.x >= 0.f ? f.x : SLOPE * f.x;
                f.y = fmaf(f.y, sc4.y, sh4.y); f.y = f.y >= 0.f ? f.y : SLOPE * f.y;
                f.z = fmaf(f.z, sc4.z, sh4.z); f.z = f.z >= 0.f ? f.z : SLOPE * f.z;
                f.w = fmaf(f.w, sc4.w, sh4.w); f.w = f.w >= 0.f ? f.w : SLOPE * f.w;
                float* d = dbuf + v * 33 + cg;
                d[0] = f.x; d[1] = f.y; d[2] = f.z; d[3] = f.w;
            }
            if (ch < 5) {
                int j = ch + 2;
#pragma unroll
                for (int r = 0; r < 8; ++r) {
                    int nb = nidxT[j * 32 + 4 * r + rsel];
                    pf[r] = *(const float4*)(h1b + (size_t)nb * 32 + cg);
                }
            }
            __syncwarp();
        }
    }
    __syncwarp();
    if (lane >= nvalid) {
#pragma unroll
        for (int c = 0; c < 32; ++c) acc[c] = 0.f;
    }
    float* st = mw;
#pragma unroll
    for (int c = 0; c < 32; ++c) st[lane * 33 + c] = acc[c];
    __syncwarp();
#pragma unroll
    for (int r = 0; r < 8; ++r) {
        int v = 4 * r + rsel;
        if (v < nvalid) {
            float4 o = make_float4(st[v * 33 + cg], st[v * 33 + cg + 1],
                                   st[v * 33 + cg + 2], st[v * 33 + cg + 3]);
            *(float4*)(h2b + (size_t)(tb + v) * 32 + cg) = o;
        }
    }
    float s = 0.f, q = 0.f;
#pragma unroll 8
    for (int v = 0; v < 32; ++v) {
        float x = st[v * 33 + lane];
        s += x;
        q = fmaf(x, x, q);
    }
    atomicAdd(&g_s2[b * 32 + lane], s);
    atomicAdd(&g_q2[b * 32 + lane], q);
#endif
}

// ---------------- BN finalize ----------------
__global__ void k_bnfin(int which, const float* __restrict__ g, const float* __restrict__ be)
{
    int i = threadIdx.x;
    if (i >= NB * 32) return;
    int c = i & 31;
    float s = which ? g_s2[i] : g_s1[i];
    float q = which ? g_q2[i] : g_q1[i];
    float mean = s / (float)V2;
    float var = q / (float)V2 - mean * mean;
    float scale = g[c] * rsqrtf(var + EPSF);
    float shift = be[c] - mean * scale;
    if (which) { g_sc2[i] = scale; g_sh2[i] = shift; }
    else       { g_sc1[i] = scale; g_sh1[i] = shift; }
}

// ---------------- BN2 + LReLU + transpose out ----------------
__global__ __launch_bounds__(256) void k_final(float* __restrict__ out)
{
    __shared__ float tile[32 * 33];
    int b = blockIdx.y, v0 = blockIdx.x * 32;
    const float* hb = g_h2 + (size_t)b * V2 * 32;
    int tid = threadIdx.x;
    for (int i = tid; i < 1024; i += 256) {
        int c = i & 31, vi = i >> 5;
        int v = v0 + vi;
        tile[vi * 33 + c] = (v < V2) ? hb[(size_t)v * 32 + c] : 0.f;
    }
    __syncthreads();
    for (int i = tid; i < 1024; i += 256) {
        int vi = i & 31, c = i >> 5;
        int v = v0 + vi;
        if (v < V2) {
            float y = fmaf(tile[vi * 33 + c], g_sc2[b * 32 + c], g_sh2[b * 32 + c]);
            out[((size_t)b * 32 + c) * V2 + v] = (y >= 0.f) ? y : SLOPE * y;
        }
    }
}

// ---------------- launch ----------------
extern "C" void kernel_launch(void* const* d_in, const int* in_sizes, int n_in,
                              void* d_out, int out_size)
{
    const float* x1   = (const float*)d_in[0];
    const float* x2   = (const float*)d_in[1];
    const int* neigh  = (const int*)d_in[2];
    const int* top    = (const int*)d_in[3];
    const int* down   = (const int*)d_in[4];
    const float* W_up = (const float*)d_in[5];
    const float* b_up = (const float*)d_in[6];
    const float* W1   = (const float*)d_in[7];
    const float* b1   = (const float*)d_in[8];
    const float* g1   = (const float*)d_in[9];
    const float* be1  = (const float*)d_in[10];
    const float* W2   = (const float*)d_in[11];
    const float* b2   = (const float*)d_in[12];
    const float* g2   = (const float*)d_in[13];
    const float* be2  = (const float*)d_in[14];
    float* out = (float*)d_out;

    const size_t ug_smem = (size_t)(7 * 64 * 32 + 224 + 8 * 32 * 65 + 8 * 32 * 33) * 4;
    const size_t c1t_smem = SM_C1_TOTAL;
    const size_t c2t_smem = SM_C2_TOTAL;
    const size_t c1f_smem = (size_t)(448 * 32 + 16 * 2112 + 16 * 224) * 4;
    const size_t c2f_smem = (size_t)(224 * 32 + 16 * 2112 + 16 * 224) * 4;
    cudaFuncSetAttribute(k_upgemm, cudaFuncAttributeMaxDynamicSharedMemorySize, (int)ug_smem);
    cudaFuncSetAttribute(k_conv1t, cudaFuncAttributeMaxDynamicSharedMemorySize, (int)c1t_smem);
    cudaFuncSetAttribute(k_conv2t, cudaFuncAttributeMaxDynamicSharedMemorySize, (int)c2t_smem);
    cudaFuncSetAttribute(k_conv1f, cudaFuncAttributeMaxDynamicSharedMemorySize, (int)c1f_smem);
    cudaFuncSetAttribute(k_conv2f, cudaFuncAttributeMaxDynamicSharedMemorySize, (int)c2f_smem);

    int nsm = 148;
    cudaDeviceGetAttribute(&nsm, cudaDevAttrMultiProcessorCount, 0);

    k_prep<<<32, 256>>>(W1, W2, W_up);

    int ug_tiles = (V1 + 31) / 32;
    dim3 gug((ug_tiles + 7) / 8, NB);
    k_upgemm<<<gug, 256, ug_smem>>>(x1, b_up);

    dim3 gsc((V2 + 255) / 256, NB);
    k_scatter<<<gsc, 256>>>(x2, top, down);

    int cv_tiles = (V2 + 31) / 32;
    dim3 gcv((cv_tiles + 15) / 16, NB);

    k_conv1t<<<nsm, 512, c1t_smem>>>(neigh, b1);
    k_conv1f<<<gcv, 512, c1f_smem>>>(neigh, b1);

    k_bnfin<<<1, 128>>>(0, g1, be1);

    k_conv2t<<<nsm, 512, c2t_smem>>>(neigh, b2);
    k_conv2f<<<gcv, 512, c2f_smem>>>(neigh, b2);

    k_bnfin<<<1, 128>>>(1, g2, be2);

    dim3 gfin((V2 + 31) / 32, NB);
    k_final<<<gfin, 256>>>(out);
}